// round 9
// baseline (speedup 1.0000x reference)
#include <cuda_runtime.h>
#include <cuda_bf16.h>

// position_encoder: out[b,s,j] = x[b,s,j] + (j even ? sin : cos)(s / 10000^((j+1)/1024))
// B=4, S=8192, D=1024, fp32.
// 512-thread blocks, 4 rows/block, 2 rows/thread (stride 2).
// Seed sincosf (fp64 theta) at row s0+r; second row via one angle-addition
// with compile-time sin/cos(2*fd_j). 8 float4 loads front-batched.

#define PE_S     8192
#define PE_D     1024
#define PE_B     4
#define PE_ROWS  4                 // rows per block
#define PE_D4    (PE_D / 4)        // 256 float4 per row

struct PETab {
    double fd[PE_D];   // 10000^(-(j+1)/1024)
    float  s2[PE_D];   // sin(2*fd_j)
    float  c2[PE_D];   // cos(2*fd_j)
};

constexpr double cexp_small(double t) {
    double r = 1.0;
    for (int k = 24; k >= 1; --k) r = 1.0 + t * r / (double)k;
    return r;
}
constexpr double csin(double x) {
    double x2 = x * x, term = x, sum = x;
    for (int k = 1; k <= 12; ++k) { term *= -x2 / (double)((2 * k) * (2 * k + 1)); sum += term; }
    return sum;
}
constexpr double ccos(double x) {
    double x2 = x * x, term = 1.0, sum = 1.0;
    for (int k = 1; k <= 12; ++k) { term *= -x2 / (double)((2 * k - 1) * (2 * k)); sum += term; }
    return sum;
}
constexpr PETab make_tab() {
    PETab t{};
    const double kexp = 13.287712379549449 / 1024.0;  // log2(10000)/1024
    const double ln2  = 0.6931471805599453;
    for (int j = 0; j < PE_D; ++j) {
        const double e = (double)(j + 1) * kexp;
        const int    n = (int)e;
        const double f = e - (double)n;
        double v = cexp_small(-f * ln2);              // 2^-frac
        for (int i = 0; i < n; ++i) v *= 0.5;         // * 2^-int (exact)
        t.fd[j] = v;
        t.s2[j] = (float)csin(2.0 * v);
        t.c2[j] = (float)ccos(2.0 * v);
    }
    return t;
}
__device__ constexpr PETab g_tab = make_tab();

__global__ __launch_bounds__(512)
void position_encoder_kernel(const float4* __restrict__ x, float4* __restrict__ out) {
    const unsigned d4 = threadIdx.x & (PE_D4 - 1);    // column group 0..255
    const unsigned r  = threadIdx.x >> 8;             // row parity 0..1
    const unsigned s  = blockIdx.x * PE_ROWS + r;     // rows s and s+2
    const unsigned j0 = d4 * 4;

    // seed at row s (fp64 theta -> fp32 sincos), rotate by 2*fd for row s+2
    float sn[4], cs[4];
#pragma unroll
    for (int c = 0; c < 4; c++)
        sincosf((float)((double)s * g_tab.fd[j0 + c]), &sn[c], &cs[c]);
    const float4 p0 = make_float4(sn[0], cs[1], sn[2], cs[3]);

    float sn2[4], cs2[4];
#pragma unroll
    for (int c = 0; c < 4; c++) {
        const float sf = g_tab.s2[j0 + c];
        const float cf = g_tab.c2[j0 + c];
        sn2[c] = fmaf(sn[c], cf,  cs[c] * sf);
        cs2[c] = fmaf(cs[c], cf, -sn[c] * sf);
    }
    const float4 p1 = make_float4(sn2[0], cs2[1], sn2[2], cs2[3]);

    // 32-bit indexing: 8.4M float4 total fits comfortably
    const unsigned bstride = (unsigned)PE_S * PE_D4;          // float4 per batch
    const unsigned base0   = s * PE_D4 + d4;                  // row s
    const unsigned base1   = base0 + 2u * PE_D4;              // row s+2
    const float4* __restrict__ xp = x;
    float4* __restrict__       op = out;

    // front-batch all 8 loads (2 rows x 4 batches), add, store
    float4 v[2 * PE_B];
#pragma unroll
    for (int b = 0; b < PE_B; b++) {
        v[2 * b + 0] = xp[base0 + (unsigned)b * bstride];
        v[2 * b + 1] = xp[base1 + (unsigned)b * bstride];
    }
#pragma unroll
    for (int b = 0; b < PE_B; b++) {
        v[2 * b + 0].x += p0.x; v[2 * b + 0].y += p0.y;
        v[2 * b + 0].z += p0.z; v[2 * b + 0].w += p0.w;
        v[2 * b + 1].x += p1.x; v[2 * b + 1].y += p1.y;
        v[2 * b + 1].z += p1.z; v[2 * b + 1].w += p1.w;
    }
#pragma unroll
    for (int b = 0; b < PE_B; b++) {
        op[base0 + (unsigned)b * bstride] = v[2 * b + 0];
        op[base1 + (unsigned)b * bstride] = v[2 * b + 1];
    }
}

extern "C" void kernel_launch(void* const* d_in, const int* in_sizes, int n_in,
                              void* d_out, int out_size) {
    (void)in_sizes; (void)n_in; (void)out_size;
    const float4* x = (const float4*)d_in[0];
    float4* out = (float4*)d_out;
    position_encoder_kernel<<<PE_S / PE_ROWS, 512>>>(x, out);
}